// round 11
// baseline (speedup 1.0000x reference)
#include <cuda_runtime.h>
#include <cuda_fp16.h>
#include <math.h>
#include <stdint.h>

// ---------------- problem constants ----------------
#define BBATCH 4
#define EE 8
#define NTOK 1024
#define DD 1024
#define HH 4096
#define MMTOK 4096          // B*N rows per expert

// ---------------- tile config ----------------
// CTA 128x128 (8 warps, 2x4), warp tile 64x32, BK=64, 3-stage ring, 2 CTAs/SM.
#define BM 128
#define BN 128
#define BK 64               // halves per k-chunk (128 B rows)
#define STAGES 3
#define APAD 72             // A smem row stride in halves (144 B)
#define WPAD 136            // W smem row stride in halves (272 B)

#define A_ST_BYTES (BM * APAD * 2)     // 18432
#define W_ST_BYTES (BK * WPAD * 2)     // 17408
#define SMEM_BYTES (STAGES * (A_ST_BYTES + W_ST_BYTES))   // 107520

// ---------------- device scratch (fp16 copies + hidden acts) ----------------
__device__ __align__(1024) __half g_h  [(size_t)EE * MMTOK * HH];
__device__ __align__(1024) __half g_xh [(size_t)BBATCH * EE * NTOK * DD];
__device__ __align__(1024) __half g_w1h[(size_t)EE * DD * HH];
__device__ __align__(1024) __half g_w2h[(size_t)EE * HH * DD];

// ---------------- helpers ----------------
__device__ __forceinline__ float gelu_tanh(float v) {
    const float c0 = 0.7978845608028654f;
    const float c1 = 0.044715f;
    float u = c0 * (v + c1 * v * v * v);
    return 0.5f * v * (1.0f + tanhf(u));
}
__device__ __forceinline__ size_t xrow_off(int m, int e) {
    return ((size_t)((m >> 10) * EE + e) * NTOK + (size_t)(m & (NTOK - 1))) * DD;
}
__device__ __forceinline__ void cp16(uint32_t smem_dst, const void* gsrc) {
    asm volatile("cp.async.cg.shared.global [%0], [%1], 16;" :: "r"(smem_dst), "l"(gsrc));
}
__device__ __forceinline__ void cp_commit() { asm volatile("cp.async.commit_group;"); }
template<int N> __device__ __forceinline__ void cp_wait() {
    asm volatile("cp.async.wait_group %0;" :: "n"(N));
}
__device__ __forceinline__ void ldmA(uint32_t* r, uint32_t addr) {
    asm volatile("ldmatrix.sync.aligned.m8n8.x4.shared.b16 {%0,%1,%2,%3}, [%4];"
                 : "=r"(r[0]), "=r"(r[1]), "=r"(r[2]), "=r"(r[3]) : "r"(addr));
}
__device__ __forceinline__ void ldmB4(uint32_t* r, uint32_t addr) {
    asm volatile("ldmatrix.sync.aligned.m8n8.x4.trans.shared.b16 {%0,%1,%2,%3}, [%4];"
                 : "=r"(r[0]), "=r"(r[1]), "=r"(r[2]), "=r"(r[3]) : "r"(addr));
}
// fp16-accumulator HMMA: acc = 2 x b32 regs (4 halves)
__device__ __forceinline__ void mma16816_f16(uint32_t* c, const uint32_t* a, const uint32_t* b) {
    asm volatile(
        "mma.sync.aligned.m16n8k16.row.col.f16.f16.f16.f16 "
        "{%0,%1}, {%2,%3,%4,%5}, {%6,%7}, {%0,%1};"
        : "+r"(c[0]), "+r"(c[1])
        : "r"(a[0]), "r"(a[1]), "r"(a[2]), "r"(a[3]), "r"(b[0]), "r"(b[1]));
}

// ---------------- prep: fp32 -> fp16 (RN) copy ----------------
__global__ __launch_bounds__(256) void to_half(const float4* __restrict__ in,
                                               __half2* __restrict__ out) {
    size_t i = (size_t)blockIdx.x * blockDim.x + threadIdx.x;
    float4 v = in[i];
    out[2 * i]     = __floats2half2_rn(v.x, v.y);
    out[2 * i + 1] = __floats2half2_rn(v.z, v.w);
}

// ---------------- main GEMM ----------------
// C[e] = act(A[e] @ W[e] + bias[e]); fp16 accumulation per BK chunk, fp32 master.
template<int K, int NC, bool A_IDX, bool C_IDX, bool GELU, class CT>
__global__ void __launch_bounds__(256, 2) ffn_gemm(
    const __half* __restrict__ A,
    const __half* __restrict__ W,
    const float* __restrict__ bias,
    CT* __restrict__ C)
{
    extern __shared__ __half smem[];

    const int tid  = threadIdx.x;
    const int lane = tid & 31;
    const int wid  = tid >> 5;
    const int wm   = wid >> 2;             // 0..1  (64 rows)
    const int wn   = wid & 3;              // 0..3  (32 cols)
    const int qr   = lane >> 2;            // 0..7
    const int qc   = lane & 3;             // 0..3

    const int e  = blockIdx.z;
    const int m0 = blockIdx.y * BM;
    const int n0 = blockIdx.x * BN;

    // ---- cp.async geometry (4 chunks of A + 4 of W per thread per stage) ----
    const int arow0 = tid >> 3, akc = (tid & 7) << 3;
    const int wrow0 = tid >> 4, wnc = (tid & 15) << 3;

    const __half* gA;   // advanced by BK per chunk
    if (A_IDX) gA = A + xrow_off(m0 + arow0, e) + akc;
    else       gA = A + ((size_t)e * MMTOK + m0 + arow0) * (size_t)K + akc;
    const __half* gW = W + (size_t)e * K * NC + n0 + (size_t)wrow0 * NC + wnc;

    const uint32_t sbase = (uint32_t)__cvta_generic_to_shared(smem);
    const uint32_t sAoff = sbase + (uint32_t)(arow0 * APAD + akc) * 2;
    const uint32_t sWoff = sbase + (uint32_t)STAGES * A_ST_BYTES
                         + (uint32_t)(wrow0 * WPAD + wnc) * 2;

    // ---- ldmatrix per-lane base offsets (halves) ----
    const int matQ = lane >> 3;
    const int rowQ = lane & 7;
    const int a_lane_off = (wm * 64 + (matQ & 1) * 8 + rowQ) * APAD + (matQ >> 1) * 8;
    const int b_lane_off = ((matQ & 1) * 8 + rowQ) * WPAD + wn * 32 + (matQ >> 1) * 8;

    float acc[4][4][4];
    #pragma unroll
    for (int i = 0; i < 4; i++)
        #pragma unroll
        for (int j = 0; j < 4; j++)
            #pragma unroll
            for (int r = 0; r < 4; r++) acc[i][j][r] = 0.0f;

    constexpr int KCH = K / BK;

    auto issue_stage = [&](int s) {
        uint32_t sa = sAoff + (uint32_t)s * A_ST_BYTES;
        uint32_t sw = sWoff + (uint32_t)s * W_ST_BYTES;
        #pragma unroll
        for (int t = 0; t < 4; t++)
            cp16(sa + (uint32_t)(t * 32 * APAD) * 2, gA + (size_t)t * 32 * K);
        #pragma unroll
        for (int t = 0; t < 4; t++)
            cp16(sw + (uint32_t)(t * 16 * WPAD) * 2, gW + (size_t)t * 16 * NC);
        gA += BK;
        gW += (size_t)BK * NC;
    };

    issue_stage(0); cp_commit();
    issue_stage(1); cp_commit();

    int s = 0;
    #pragma unroll 1
    for (int c = 0; c < KCH; c++) {
        cp_wait<1>();             // stage s (chunk c) resident
        __syncthreads();          // all warps done with the stage being overwritten

        if (c + 2 < KCH) issue_stage((s + 2 >= STAGES) ? s + 2 - STAGES : s + 2);
        cp_commit();              // one group per iteration (empty at the tail)

        const uint32_t asb = sbase + (uint32_t)s * A_ST_BYTES + (uint32_t)a_lane_off * 2;
        const uint32_t wsb = sbase + (uint32_t)STAGES * A_ST_BYTES
                           + (uint32_t)s * W_ST_BYTES + (uint32_t)b_lane_off * 2;

        // fp16 chunk accumulators (zeroed each chunk)
        uint32_t acc16[4][4][2];
        #pragma unroll
        for (int i = 0; i < 4; i++)
            #pragma unroll
            for (int j = 0; j < 4; j++) { acc16[i][j][0] = 0u; acc16[i][j][1] = 0u; }

        #pragma unroll
        for (int kk = 0; kk < BK; kk += 16) {
            uint32_t a[4][4];
            uint32_t b[2][4];
            #pragma unroll
            for (int i = 0; i < 4; i++)
                ldmA(a[i], asb + (uint32_t)(i * 16 * APAD + kk) * 2);
            #pragma unroll
            for (int j = 0; j < 2; j++)
                ldmB4(b[j], wsb + (uint32_t)(kk * WPAD + j * 16) * 2);
            #pragma unroll
            for (int i = 0; i < 4; i++)
                #pragma unroll
                for (int j = 0; j < 4; j++)
                    mma16816_f16(acc16[i][j], a[i], &b[j >> 1][(j & 1) * 2]);
        }

        // flush fp16 chunk accumulators into fp32 master
        #pragma unroll
        for (int i = 0; i < 4; i++)
            #pragma unroll
            for (int j = 0; j < 4; j++) {
                float2 lo = __half22float2(*(__half2*)&acc16[i][j][0]);
                float2 hi = __half22float2(*(__half2*)&acc16[i][j][1]);
                acc[i][j][0] += lo.x;
                acc[i][j][1] += lo.y;
                acc[i][j][2] += hi.x;
                acc[i][j][3] += hi.y;
            }

        if (++s == STAGES) s = 0;
    }

    // ---------------- epilogue: bias (+gelu) + store ----------------
    #pragma unroll
    for (int i = 0; i < 4; i++) {
        #pragma unroll
        for (int hh = 0; hh < 2; hh++) {
            int m = m0 + wm * 64 + i * 16 + hh * 8 + qr;
            size_t crow;
            if (C_IDX) crow = xrow_off(m, e);
            else       crow = ((size_t)e * MMTOK + m) * (size_t)NC;
            #pragma unroll
            for (int j = 0; j < 4; j++) {
                int n = n0 + wn * 32 + j * 8 + qc * 2;
                float2 bv = *(const float2*)(bias + (size_t)e * NC + n);
                float vx = acc[i][j][hh * 2 + 0] + bv.x;
                float vy = acc[i][j][hh * 2 + 1] + bv.y;
                if (GELU) { vx = gelu_tanh(vx); vy = gelu_tanh(vy); }
                if constexpr (sizeof(CT) == 2) {
                    *(__half2*)((__half*)C + crow + n) = __floats2half2_rn(vx, vy);
                } else {
                    float2 o; o.x = vx; o.y = vy;
                    *(float2*)((float*)C + crow + n) = o;
                }
            }
        }
    }
}

// ---------------- host ----------------
extern "C" void kernel_launch(void* const* d_in, const int* in_sizes, int n_in,
                              void* d_out, int out_size)
{
    const float* x  = (const float*)d_in[0];   // (B,E,N,D)
    const float* w1 = (const float*)d_in[1];   // (E,D,H)
    const float* b1 = (const float*)d_in[2];   // (E,H)
    const float* w2 = (const float*)d_in[3];   // (E,H,D)
    const float* b2 = (const float*)d_in[4];   // (E,D)
    float* out = (float*)d_out;                // (B,E,N,D)

    void *ph, *pxh, *pw1, *pw2;
    cudaGetSymbolAddress(&ph,  g_h);
    cudaGetSymbolAddress(&pxh, g_xh);
    cudaGetSymbolAddress(&pw1, g_w1h);
    cudaGetSymbolAddress(&pw2, g_w2h);
    __half* h   = (__half*)ph;
    __half* xh  = (__half*)pxh;
    __half* w1h = (__half*)pw1;
    __half* w2h = (__half*)pw2;

    // prep: fp16 conversion (RN)
    {
        size_t nx = (size_t)BBATCH * EE * NTOK * DD / 4;
        size_t nw = (size_t)EE * DD * HH / 4;
        to_half<<<(unsigned)(nx / 256), 256>>>((const float4*)x,  (__half2*)xh);
        to_half<<<(unsigned)(nw / 256), 256>>>((const float4*)w1, (__half2*)w1h);
        to_half<<<(unsigned)(nw / 256), 256>>>((const float4*)w2, (__half2*)w2h);
    }

    cudaFuncSetAttribute(ffn_gemm<DD, HH, true,  false, true,  __half>,
                         cudaFuncAttributeMaxDynamicSharedMemorySize, SMEM_BYTES);
    cudaFuncSetAttribute(ffn_gemm<HH, DD, false, true,  false, float>,
                         cudaFuncAttributeMaxDynamicSharedMemorySize, SMEM_BYTES);

    // GEMM1: h = fp16(gelu(x @ w1 + b1))
    ffn_gemm<DD, HH, true, false, true, __half>
        <<<dim3(HH / BN, MMTOK / BM, EE), 256, SMEM_BYTES>>>(xh, w1h, b1, h);
    // GEMM2: out = h @ w2 + b2
    ffn_gemm<HH, DD, false, true, false, float>
        <<<dim3(DD / BN, MMTOK / BM, EE), 256, SMEM_BYTES>>>(h, w2h, b2, out);
}

// round 13
// speedup vs baseline: 1.0612x; 1.0612x over previous
#include <cuda_runtime.h>
#include <cuda_fp16.h>
#include <math.h>
#include <stdint.h>

// ---------------- problem constants ----------------
#define BBATCH 4
#define EE 8
#define NTOK 1024
#define DD 1024
#define HH 4096
#define MMTOK 4096          // B*N rows per expert

// ---------------- tile config ----------------
// CTA 128x128 (8 warps, 2x4), warp tile 64x32, BK=32, 6-stage ring, 2 CTAs/SM.
// Chunks processed in PAIRS: one cp_wait + one __syncthreads per 2 chunks.
#define BM 128
#define BN 128
#define BK 32               // halves per k-chunk (64 B rows)
#define STAGES 6
#define APAD 40             // A smem row stride in halves (80 B)  - conflict-free
#define WPAD 136            // W smem row stride in halves (272 B) - conflict-free

#define A_ST_BYTES (BM * APAD * 2)     // 10240
#define W_ST_BYTES (BK * WPAD * 2)     // 8704
#define SMEM_BYTES (STAGES * (A_ST_BYTES + W_ST_BYTES))   // 113664

// ---------------- device scratch (fp16 copies + hidden acts) ----------------
__device__ __align__(1024) __half g_h  [(size_t)EE * MMTOK * HH];
__device__ __align__(1024) __half g_xh [(size_t)BBATCH * EE * NTOK * DD];
__device__ __align__(1024) __half g_w1h[(size_t)EE * DD * HH];
__device__ __align__(1024) __half g_w2h[(size_t)EE * HH * DD];

// ---------------- helpers ----------------
__device__ __forceinline__ float gelu_tanh(float v) {
    const float c0 = 0.7978845608028654f;
    const float c1 = 0.044715f;
    float u = c0 * (v + c1 * v * v * v);
    return 0.5f * v * (1.0f + tanhf(u));
}
__device__ __forceinline__ size_t xrow_off(int m, int e) {
    return ((size_t)((m >> 10) * EE + e) * NTOK + (size_t)(m & (NTOK - 1))) * DD;
}
__device__ __forceinline__ void cp16(uint32_t smem_dst, const void* gsrc) {
    asm volatile("cp.async.cg.shared.global [%0], [%1], 16;" :: "r"(smem_dst), "l"(gsrc));
}
__device__ __forceinline__ void cp_commit() { asm volatile("cp.async.commit_group;"); }
template<int N> __device__ __forceinline__ void cp_wait() {
    asm volatile("cp.async.wait_group %0;" :: "n"(N));
}
__device__ __forceinline__ void ldmA(uint32_t* r, uint32_t addr) {
    asm volatile("ldmatrix.sync.aligned.m8n8.x4.shared.b16 {%0,%1,%2,%3}, [%4];"
                 : "=r"(r[0]), "=r"(r[1]), "=r"(r[2]), "=r"(r[3]) : "r"(addr));
}
__device__ __forceinline__ void ldmB4(uint32_t* r, uint32_t addr) {
    asm volatile("ldmatrix.sync.aligned.m8n8.x4.trans.shared.b16 {%0,%1,%2,%3}, [%4];"
                 : "=r"(r[0]), "=r"(r[1]), "=r"(r[2]), "=r"(r[3]) : "r"(addr));
}
__device__ __forceinline__ void mma16816(float* c, const uint32_t* a, const uint32_t* b) {
    asm volatile(
        "mma.sync.aligned.m16n8k16.row.col.f32.f16.f16.f32 "
        "{%0,%1,%2,%3}, {%4,%5,%6,%7}, {%8,%9}, {%0,%1,%2,%3};"
        : "+f"(c[0]), "+f"(c[1]), "+f"(c[2]), "+f"(c[3])
        : "r"(a[0]), "r"(a[1]), "r"(a[2]), "r"(a[3]), "r"(b[0]), "r"(b[1]));
}

// ---------------- prep: fp32 -> fp16 (RN) copy ----------------
__global__ __launch_bounds__(256) void to_half(const float4* __restrict__ in,
                                               __half2* __restrict__ out) {
    size_t i = (size_t)blockIdx.x * blockDim.x + threadIdx.x;
    float4 v = in[i];
    out[2 * i]     = __floats2half2_rn(v.x, v.y);
    out[2 * i + 1] = __floats2half2_rn(v.z, v.w);
}

// ---------------- main GEMM ----------------
// C[e] = act(A[e] @ W[e] + bias[e]);  warp tile 64x32, fp32 accumulators.
template<int K, int NC, bool A_IDX, bool C_IDX, bool GELU, class CT>
__global__ void __launch_bounds__(256, 2) ffn_gemm(
    const __half* __restrict__ A,
    const __half* __restrict__ W,
    const float* __restrict__ bias,
    CT* __restrict__ C)
{
    extern __shared__ __half smem[];

    const int tid  = threadIdx.x;
    const int lane = tid & 31;
    const int wid  = tid >> 5;
    const int wm   = wid >> 2;             // 0..1  (64 rows)
    const int wn   = wid & 3;              // 0..3  (32 cols)
    const int qr   = lane >> 2;            // 0..7
    const int qc   = lane & 3;             // 0..3

    const int e  = blockIdx.z;
    const int m0 = blockIdx.y * BM;
    const int n0 = blockIdx.x * BN;

    // ---- cp.async geometry (2 chunks of A + 2 of W per thread per stage) ----
    const int arow0 = tid >> 2, akc = (tid & 3) << 3;
    const int wrow0 = tid >> 4, wnc = (tid & 15) << 3;

    const __half* gA;   // advanced by BK per issued stage
    if (A_IDX) gA = A + xrow_off(m0 + arow0, e) + akc;
    else       gA = A + ((size_t)e * MMTOK + m0 + arow0) * (size_t)K + akc;
    const __half* gW = W + (size_t)e * K * NC + n0 + (size_t)wrow0 * NC + wnc;

    const uint32_t sbase = (uint32_t)__cvta_generic_to_shared(smem);
    const uint32_t sAoff = sbase + (uint32_t)(arow0 * APAD + akc) * 2;
    const uint32_t sWoff = sbase + (uint32_t)STAGES * A_ST_BYTES
                         + (uint32_t)(wrow0 * WPAD + wnc) * 2;

    // ---- ldmatrix per-lane base offsets (halves) ----
    const int matQ = lane >> 3;
    const int rowQ = lane & 7;
    const int a_lane_off = (wm * 64 + (matQ & 1) * 8 + rowQ) * APAD + (matQ >> 1) * 8;
    const int b_lane_off = ((matQ & 1) * 8 + rowQ) * WPAD + wn * 32 + (matQ >> 1) * 8;

    float acc[4][4][4];
    #pragma unroll
    for (int i = 0; i < 4; i++)
        #pragma unroll
        for (int j = 0; j < 4; j++)
            #pragma unroll
            for (int r = 0; r < 4; r++) acc[i][j][r] = 0.0f;

    constexpr int KCH = K / BK;            // 32 (GEMM1) / 128 (GEMM2); even

    auto issue_stage = [&](int s) {        // one BK chunk into ring stage s
        uint32_t sa = sAoff + (uint32_t)s * A_ST_BYTES;
        uint32_t sw = sWoff + (uint32_t)s * W_ST_BYTES;
        #pragma unroll
        for (int t = 0; t < 2; t++)
            cp16(sa + (uint32_t)(t * 64 * APAD) * 2, gA + (size_t)t * 64 * K);
        #pragma unroll
        for (int t = 0; t < 2; t++)
            cp16(sw + (uint32_t)(t * 16 * WPAD) * 2, gW + (size_t)t * 16 * NC);
        gA += BK;
        gW += (size_t)BK * NC;
    };

    auto consume_chunk = [&](int s) {      // MMAs for ring stage s
        const uint32_t asb = sbase + (uint32_t)s * A_ST_BYTES + (uint32_t)a_lane_off * 2;
        const uint32_t wsb = sbase + (uint32_t)STAGES * A_ST_BYTES
                           + (uint32_t)s * W_ST_BYTES + (uint32_t)b_lane_off * 2;
        #pragma unroll
        for (int kk = 0; kk < BK; kk += 16) {
            uint32_t a[4][4];
            uint32_t b[2][4];
            #pragma unroll
            for (int i = 0; i < 4; i++)
                ldmA(a[i], asb + (uint32_t)(i * 16 * APAD + kk) * 2);
            #pragma unroll
            for (int j = 0; j < 2; j++)
                ldmB4(b[j], wsb + (uint32_t)(kk * WPAD + j * 16) * 2);
            #pragma unroll
            for (int i = 0; i < 4; i++)
                #pragma unroll
                for (int j = 0; j < 4; j++)
                    mma16816(acc[i][j], a[i], &b[j >> 1][(j & 1) * 2]);
        }
    };

    // prologue: chunks 0..3 into stages 0..3, TWO chunks per commit group
    issue_stage(0); issue_stage(1); cp_commit();   // group {0,1}
    issue_stage(2); issue_stage(3); cp_commit();   // group {2,3}

    int s = 0;
    #pragma unroll 1
    for (int c = 0; c < KCH; c += 2) {
        cp_wait<1>();             // group {c, c+1} resident ({c+2, c+3} may pend)
        __syncthreads();          // publish all threads' copies; also protects the
                                  // stages (last read 2 iterations ago) we now overwrite
        // issue next pair into stages s+4, s+5 (mod 6)
        if (c + 4 < KCH) {
            int w0 = s + 4; if (w0 >= STAGES) w0 -= STAGES;
            int w1 = s + 5; if (w1 >= STAGES) w1 -= STAGES;
            issue_stage(w0);
            issue_stage(w1);
        }
        cp_commit();              // one group per iteration (empty near the tail)

        consume_chunk(s);
        int s1 = s + 1; if (s1 >= STAGES) s1 -= STAGES;
        consume_chunk(s1);

        s += 2; if (s >= STAGES) s -= STAGES;
    }

    // ---------------- epilogue: bias (+gelu) + store ----------------
    #pragma unroll
    for (int i = 0; i < 4; i++) {
        #pragma unroll
        for (int hh = 0; hh < 2; hh++) {
            int m = m0 + wm * 64 + i * 16 + hh * 8 + qr;
            size_t crow;
            if (C_IDX) crow = xrow_off(m, e);
            else       crow = ((size_t)e * MMTOK + m) * (size_t)NC;
            #pragma unroll
            for (int j = 0; j < 4; j++) {
                int n = n0 + wn * 32 + j * 8 + qc * 2;
                float2 bv = *(const float2*)(bias + (size_t)e * NC + n);
                float vx = acc[i][j][hh * 2 + 0] + bv.x;
                float vy = acc[i][j][hh * 2 + 1] + bv.y;
                if (GELU) { vx = gelu_tanh(vx); vy = gelu_tanh(vy); }
                if constexpr (sizeof(CT) == 2) {
                    *(__half2*)((__half*)C + crow + n) = __floats2half2_rn(vx, vy);
                } else {
                    float2 o; o.x = vx; o.y = vy;
                    *(float2*)((float*)C + crow + n) = o;
                }
            }
        }
    }
}

// ---------------- host ----------------
extern "C" void kernel_launch(void* const* d_in, const int* in_sizes, int n_in,
                              void* d_out, int out_size)
{
    const float* x  = (const float*)d_in[0];   // (B,E,N,D)
    const float* w1 = (const float*)d_in[1];   // (E,D,H)
    const float* b1 = (const float*)d_in[2];   // (E,H)
    const float* w2 = (const float*)d_in[3];   // (E,H,D)
    const float* b2 = (const float*)d_in[4];   // (E,D)
    float* out = (float*)d_out;                // (B,E,N,D)

    void *ph, *pxh, *pw1, *pw2;
    cudaGetSymbolAddress(&ph,  g_h);
    cudaGetSymbolAddress(&pxh, g_xh);
    cudaGetSymbolAddress(&pw1, g_w1h);
    cudaGetSymbolAddress(&pw2, g_w2h);
    __half* h   = (__half*)ph;
    __half* xh  = (__half*)pxh;
    __half* w1h = (__half*)pw1;
    __half* w2h = (__half*)pw2;

    // prep: fp16 conversion (RN)
    {
        size_t nx = (size_t)BBATCH * EE * NTOK * DD / 4;
        size_t nw = (size_t)EE * DD * HH / 4;
        to_half<<<(unsigned)(nx / 256), 256>>>((const float4*)x,  (__half2*)xh);
        to_half<<<(unsigned)(nw / 256), 256>>>((const float4*)w1, (__half2*)w1h);
        to_half<<<(unsigned)(nw / 256), 256>>>((const float4*)w2, (__half2*)w2h);
    }

    cudaFuncSetAttribute(ffn_gemm<DD, HH, true,  false, true,  __half>,
                         cudaFuncAttributeMaxDynamicSharedMemorySize, SMEM_BYTES);
    cudaFuncSetAttribute(ffn_gemm<HH, DD, false, true,  false, float>,
                         cudaFuncAttributeMaxDynamicSharedMemorySize, SMEM_BYTES);

    // GEMM1: h = fp16(gelu(x @ w1 + b1))
    ffn_gemm<DD, HH, true, false, true, __half>
        <<<dim3(HH / BN, MMTOK / BM, EE), 256, SMEM_BYTES>>>(xh, w1h, b1, h);
    // GEMM2: out = h @ w2 + b2
    ffn_gemm<HH, DD, false, true, false, float>
        <<<dim3(DD / BN, MMTOK / BM, EE), 256, SMEM_BYTES>>>(h, w2h, b2, out);
}

// round 14
// speedup vs baseline: 1.0612x; 1.0000x over previous
#include <cuda_runtime.h>
#include <cuda_fp16.h>
#include <math.h>
#include <stdint.h>

// ---------------- problem constants ----------------
#define BBATCH 4
#define EE 8
#define NTOK 1024
#define DD 1024
#define HH 4096
#define MMTOK 4096          // B*N rows per expert

// ---------------- tile config ----------------
// CTA 128x128 (8 warps, 2x4), warp tile 64x32, BK=32, 6-stage ring, 2 CTAs/SM.
// Chunks processed in PAIRS: one cp_wait + one __syncthreads per 2 chunks.
#define BM 128
#define BN 128
#define BK 32               // halves per k-chunk (64 B rows)
#define STAGES 6
#define APAD 40             // A smem row stride in halves (80 B)  - conflict-free
#define WPAD 136            // W smem row stride in halves (272 B) - conflict-free

#define A_ST_BYTES (BM * APAD * 2)     // 10240
#define W_ST_BYTES (BK * WPAD * 2)     // 8704
#define SMEM_BYTES (STAGES * (A_ST_BYTES + W_ST_BYTES))   // 113664

// ---------------- device scratch (fp16 copies + hidden acts) ----------------
__device__ __align__(1024) __half g_h  [(size_t)EE * MMTOK * HH];
__device__ __align__(1024) __half g_xh [(size_t)BBATCH * EE * NTOK * DD];
__device__ __align__(1024) __half g_w1h[(size_t)EE * DD * HH];
__device__ __align__(1024) __half g_w2h[(size_t)EE * HH * DD];

// ---------------- helpers ----------------
__device__ __forceinline__ float gelu_tanh(float v) {
    const float c0 = 0.7978845608028654f;
    const float c1 = 0.044715f;
    float u = c0 * (v + c1 * v * v * v);
    return 0.5f * v * (1.0f + tanhf(u));
}
__device__ __forceinline__ size_t xrow_off(int m, int e) {
    return ((size_t)((m >> 10) * EE + e) * NTOK + (size_t)(m & (NTOK - 1))) * DD;
}
__device__ __forceinline__ void cp16(uint32_t smem_dst, const void* gsrc) {
    asm volatile("cp.async.cg.shared.global [%0], [%1], 16;" :: "r"(smem_dst), "l"(gsrc));
}
__device__ __forceinline__ void cp_commit() { asm volatile("cp.async.commit_group;"); }
template<int N> __device__ __forceinline__ void cp_wait() {
    asm volatile("cp.async.wait_group %0;" :: "n"(N));
}
__device__ __forceinline__ void ldmA(uint32_t* r, uint32_t addr) {
    asm volatile("ldmatrix.sync.aligned.m8n8.x4.shared.b16 {%0,%1,%2,%3}, [%4];"
                 : "=r"(r[0]), "=r"(r[1]), "=r"(r[2]), "=r"(r[3]) : "r"(addr));
}
__device__ __forceinline__ void ldmB4(uint32_t* r, uint32_t addr) {
    asm volatile("ldmatrix.sync.aligned.m8n8.x4.trans.shared.b16 {%0,%1,%2,%3}, [%4];"
                 : "=r"(r[0]), "=r"(r[1]), "=r"(r[2]), "=r"(r[3]) : "r"(addr));
}
__device__ __forceinline__ void mma16816(float* c, const uint32_t* a, const uint32_t* b) {
    asm volatile(
        "mma.sync.aligned.m16n8k16.row.col.f32.f16.f16.f32 "
        "{%0,%1,%2,%3}, {%4,%5,%6,%7}, {%8,%9}, {%0,%1,%2,%3};"
        : "+f"(c[0]), "+f"(c[1]), "+f"(c[2]), "+f"(c[3])
        : "r"(a[0]), "r"(a[1]), "r"(a[2]), "r"(a[3]), "r"(b[0]), "r"(b[1]));
}

// ---------------- prep: fp32 -> fp16 (RN) copy ----------------
__global__ __launch_bounds__(256) void to_half(const float4* __restrict__ in,
                                               __half2* __restrict__ out) {
    size_t i = (size_t)blockIdx.x * blockDim.x + threadIdx.x;
    float4 v = in[i];
    out[2 * i]     = __floats2half2_rn(v.x, v.y);
    out[2 * i + 1] = __floats2half2_rn(v.z, v.w);
}

// ---------------- main GEMM ----------------
// C[e] = act(A[e] @ W[e] + bias[e]);  warp tile 64x32, fp32 accumulators.
template<int K, int NC, bool A_IDX, bool C_IDX, bool GELU, class CT>
__global__ void __launch_bounds__(256, 2) ffn_gemm(
    const __half* __restrict__ A,
    const __half* __restrict__ W,
    const float* __restrict__ bias,
    CT* __restrict__ C)
{
    extern __shared__ __half smem[];

    const int tid  = threadIdx.x;
    const int lane = tid & 31;
    const int wid  = tid >> 5;
    const int wm   = wid >> 2;             // 0..1  (64 rows)
    const int wn   = wid & 3;              // 0..3  (32 cols)
    const int qr   = lane >> 2;            // 0..7
    const int qc   = lane & 3;             // 0..3

    const int e  = blockIdx.z;
    const int m0 = blockIdx.y * BM;
    const int n0 = blockIdx.x * BN;

    // ---- cp.async geometry (2 chunks of A + 2 of W per thread per stage) ----
    const int arow0 = tid >> 2, akc = (tid & 3) << 3;
    const int wrow0 = tid >> 4, wnc = (tid & 15) << 3;

    const __half* gA;   // advanced by BK per issued stage
    if (A_IDX) gA = A + xrow_off(m0 + arow0, e) + akc;
    else       gA = A + ((size_t)e * MMTOK + m0 + arow0) * (size_t)K + akc;
    const __half* gW = W + (size_t)e * K * NC + n0 + (size_t)wrow0 * NC + wnc;

    const uint32_t sbase = (uint32_t)__cvta_generic_to_shared(smem);
    const uint32_t sAoff = sbase + (uint32_t)(arow0 * APAD + akc) * 2;
    const uint32_t sWoff = sbase + (uint32_t)STAGES * A_ST_BYTES
                         + (uint32_t)(wrow0 * WPAD + wnc) * 2;

    // ---- ldmatrix per-lane base offsets (halves) ----
    const int matQ = lane >> 3;
    const int rowQ = lane & 7;
    const int a_lane_off = (wm * 64 + (matQ & 1) * 8 + rowQ) * APAD + (matQ >> 1) * 8;
    const int b_lane_off = ((matQ & 1) * 8 + rowQ) * WPAD + wn * 32 + (matQ >> 1) * 8;

    float acc[4][4][4];
    #pragma unroll
    for (int i = 0; i < 4; i++)
        #pragma unroll
        for (int j = 0; j < 4; j++)
            #pragma unroll
            for (int r = 0; r < 4; r++) acc[i][j][r] = 0.0f;

    constexpr int KCH = K / BK;            // 32 (GEMM1) / 128 (GEMM2); even

    auto issue_stage = [&](int s) {        // one BK chunk into ring stage s
        uint32_t sa = sAoff + (uint32_t)s * A_ST_BYTES;
        uint32_t sw = sWoff + (uint32_t)s * W_ST_BYTES;
        #pragma unroll
        for (int t = 0; t < 2; t++)
            cp16(sa + (uint32_t)(t * 64 * APAD) * 2, gA + (size_t)t * 64 * K);
        #pragma unroll
        for (int t = 0; t < 2; t++)
            cp16(sw + (uint32_t)(t * 16 * WPAD) * 2, gW + (size_t)t * 16 * NC);
        gA += BK;
        gW += (size_t)BK * NC;
    };

    auto consume_chunk = [&](int s) {      // MMAs for ring stage s
        const uint32_t asb = sbase + (uint32_t)s * A_ST_BYTES + (uint32_t)a_lane_off * 2;
        const uint32_t wsb = sbase + (uint32_t)STAGES * A_ST_BYTES
                           + (uint32_t)s * W_ST_BYTES + (uint32_t)b_lane_off * 2;
        #pragma unroll
        for (int kk = 0; kk < BK; kk += 16) {
            uint32_t a[4][4];
            uint32_t b[2][4];
            #pragma unroll
            for (int i = 0; i < 4; i++)
                ldmA(a[i], asb + (uint32_t)(i * 16 * APAD + kk) * 2);
            #pragma unroll
            for (int j = 0; j < 2; j++)
                ldmB4(b[j], wsb + (uint32_t)(kk * WPAD + j * 16) * 2);
            #pragma unroll
            for (int i = 0; i < 4; i++)
                #pragma unroll
                for (int j = 0; j < 4; j++)
                    mma16816(acc[i][j], a[i], &b[j >> 1][(j & 1) * 2]);
        }
    };

    // prologue: chunks 0..3 into stages 0..3, TWO chunks per commit group
    issue_stage(0); issue_stage(1); cp_commit();   // group {0,1}
    issue_stage(2); issue_stage(3); cp_commit();   // group {2,3}

    int s = 0;
    #pragma unroll 1
    for (int c = 0; c < KCH; c += 2) {
        cp_wait<1>();             // group {c, c+1} resident ({c+2, c+3} may pend)
        __syncthreads();          // publish all threads' copies; also protects the
                                  // stages (last read 2 iterations ago) we now overwrite
        // issue next pair into stages s+4, s+5 (mod 6)
        if (c + 4 < KCH) {
            int w0 = s + 4; if (w0 >= STAGES) w0 -= STAGES;
            int w1 = s + 5; if (w1 >= STAGES) w1 -= STAGES;
            issue_stage(w0);
            issue_stage(w1);
        }
        cp_commit();              // one group per iteration (empty near the tail)

        consume_chunk(s);
        int s1 = s + 1; if (s1 >= STAGES) s1 -= STAGES;
        consume_chunk(s1);

        s += 2; if (s >= STAGES) s -= STAGES;
    }

    // ---------------- epilogue: bias (+gelu) + store ----------------
    #pragma unroll
    for (int i = 0; i < 4; i++) {
        #pragma unroll
        for (int hh = 0; hh < 2; hh++) {
            int m = m0 + wm * 64 + i * 16 + hh * 8 + qr;
            size_t crow;
            if (C_IDX) crow = xrow_off(m, e);
            else       crow = ((size_t)e * MMTOK + m) * (size_t)NC;
            #pragma unroll
            for (int j = 0; j < 4; j++) {
                int n = n0 + wn * 32 + j * 8 + qc * 2;
                float2 bv = *(const float2*)(bias + (size_t)e * NC + n);
                float vx = acc[i][j][hh * 2 + 0] + bv.x;
                float vy = acc[i][j][hh * 2 + 1] + bv.y;
                if (GELU) { vx = gelu_tanh(vx); vy = gelu_tanh(vy); }
                if constexpr (sizeof(CT) == 2) {
                    *(__half2*)((__half*)C + crow + n) = __floats2half2_rn(vx, vy);
                } else {
                    float2 o; o.x = vx; o.y = vy;
                    *(float2*)((float*)C + crow + n) = o;
                }
            }
        }
    }
}

// ---------------- host ----------------
extern "C" void kernel_launch(void* const* d_in, const int* in_sizes, int n_in,
                              void* d_out, int out_size)
{
    const float* x  = (const float*)d_in[0];   // (B,E,N,D)
    const float* w1 = (const float*)d_in[1];   // (E,D,H)
    const float* b1 = (const float*)d_in[2];   // (E,H)
    const float* w2 = (const float*)d_in[3];   // (E,H,D)
    const float* b2 = (const float*)d_in[4];   // (E,D)
    float* out = (float*)d_out;                // (B,E,N,D)

    void *ph, *pxh, *pw1, *pw2;
    cudaGetSymbolAddress(&ph,  g_h);
    cudaGetSymbolAddress(&pxh, g_xh);
    cudaGetSymbolAddress(&pw1, g_w1h);
    cudaGetSymbolAddress(&pw2, g_w2h);
    __half* h   = (__half*)ph;
    __half* xh  = (__half*)pxh;
    __half* w1h = (__half*)pw1;
    __half* w2h = (__half*)pw2;

    // prep: fp16 conversion (RN)
    {
        size_t nx = (size_t)BBATCH * EE * NTOK * DD / 4;
        size_t nw = (size_t)EE * DD * HH / 4;
        to_half<<<(unsigned)(nx / 256), 256>>>((const float4*)x,  (__half2*)xh);
        to_half<<<(unsigned)(nw / 256), 256>>>((const float4*)w1, (__half2*)w1h);
        to_half<<<(unsigned)(nw / 256), 256>>>((const float4*)w2, (__half2*)w2h);
    }

    cudaFuncSetAttribute(ffn_gemm<DD, HH, true,  false, true,  __half>,
                         cudaFuncAttributeMaxDynamicSharedMemorySize, SMEM_BYTES);
    cudaFuncSetAttribute(ffn_gemm<HH, DD, false, true,  false, float>,
                         cudaFuncAttributeMaxDynamicSharedMemorySize, SMEM_BYTES);

    // GEMM1: h = fp16(gelu(x @ w1 + b1))
    ffn_gemm<DD, HH, true, false, true, __half>
        <<<dim3(HH / BN, MMTOK / BM, EE), 256, SMEM_BYTES>>>(xh, w1h, b1, h);
    // GEMM2: out = h @ w2 + b2
    ffn_gemm<HH, DD, false, true, false, float>
        <<<dim3(DD / BN, MMTOK / BM, EE), 256, SMEM_BYTES>>>(h, w2h, b2, out);
}

// round 15
// speedup vs baseline: 1.3127x; 1.2370x over previous
#include <cuda_runtime.h>
#include <cuda_fp16.h>
#include <math.h>
#include <stdint.h>

// ---------------- problem constants ----------------
#define BBATCH 4
#define EE 8
#define NTOK 1024
#define DD 1024
#define HH 4096
#define MMTOK 4096          // B*N rows per expert

// ---------------- tile config (R7 core) ----------------
#define BM 128
#define BN 128
#define BK 64               // halves per k-chunk (128 B rows)
#define STAGES 3
#define APAD 72             // A smem row stride in halves (144 B)
#define WPAD 136            // W smem row stride in halves (272 B)

#define A_ST_BYTES (BM * APAD * 2)     // 18432
#define W_ST_BYTES (BK * WPAD * 2)     // 17408
#define SMEM_BYTES (STAGES * (A_ST_BYTES + W_ST_BYTES))   // 107520

// ---------------- device scratch (fp16 copies + hidden acts) ----------------
__device__ __align__(1024) __half g_h  [(size_t)EE * MMTOK * HH];
__device__ __align__(1024) __half g_xh [(size_t)BBATCH * EE * NTOK * DD];
__device__ __align__(1024) __half g_w1h[(size_t)EE * DD * HH];
__device__ __align__(1024) __half g_w2h[(size_t)EE * HH * DD];

// ---------------- helpers ----------------
__device__ __forceinline__ float gelu_tanh(float v) {
    const float c0 = 0.7978845608028654f;
    const float c1 = 0.044715f;
    float u = c0 * (v + c1 * v * v * v);
    return 0.5f * v * (1.0f + tanhf(u));
}
__device__ __forceinline__ size_t xrow_off(int m, int e) {
    return ((size_t)((m >> 10) * EE + e) * NTOK + (size_t)(m & (NTOK - 1))) * DD;
}
__device__ __forceinline__ void cp16(uint32_t smem_dst, const void* gsrc) {
    asm volatile("cp.async.cg.shared.global [%0], [%1], 16;" :: "r"(smem_dst), "l"(gsrc));
}
__device__ __forceinline__ void cp_commit() { asm volatile("cp.async.commit_group;"); }
template<int N> __device__ __forceinline__ void cp_wait() {
    asm volatile("cp.async.wait_group %0;" :: "n"(N));
}
__device__ __forceinline__ void ldmA(uint32_t* r, uint32_t addr) {
    asm volatile("ldmatrix.sync.aligned.m8n8.x4.shared.b16 {%0,%1,%2,%3}, [%4];"
                 : "=r"(r[0]), "=r"(r[1]), "=r"(r[2]), "=r"(r[3]) : "r"(addr));
}
__device__ __forceinline__ void ldmB4(uint32_t* r, uint32_t addr) {
    asm volatile("ldmatrix.sync.aligned.m8n8.x4.trans.shared.b16 {%0,%1,%2,%3}, [%4];"
                 : "=r"(r[0]), "=r"(r[1]), "=r"(r[2]), "=r"(r[3]) : "r"(addr));
}
__device__ __forceinline__ void mma16816(float* c, const uint32_t* a, const uint32_t* b) {
    asm volatile(
        "mma.sync.aligned.m16n8k16.row.col.f32.f16.f16.f32 "
        "{%0,%1,%2,%3}, {%4,%5,%6,%7}, {%8,%9}, {%0,%1,%2,%3};"
        : "+f"(c[0]), "+f"(c[1]), "+f"(c[2]), "+f"(c[3])
        : "r"(a[0]), "r"(a[1]), "r"(a[2]), "r"(a[3]), "r"(b[0]), "r"(b[1]));
}

// ---------------- prep: one fused fp32 -> fp16 (RN) conversion pass ----------------
#define NX4 ((size_t)BBATCH * EE * NTOK * DD / 4)   // 8388608 float4
#define NW4 ((size_t)EE * DD * HH / 4)              // 8388608 float4
__global__ __launch_bounds__(256) void to_half_all(
    const float4* __restrict__ x,  __half2* __restrict__ xh,
    const float4* __restrict__ w1, __half2* __restrict__ w1h,
    const float4* __restrict__ w2, __half2* __restrict__ w2h)
{
    size_t i = (size_t)blockIdx.x * blockDim.x + threadIdx.x;
    const float4* src;
    __half2* dst;
    size_t j;
    if (i < NX4)             { src = x;  dst = xh;  j = i; }
    else if (i < NX4 + NW4)  { src = w1; dst = w1h; j = i - NX4; }
    else                     { src = w2; dst = w2h; j = i - NX4 - NW4; }
    float4 v = src[j];
    dst[2 * j]     = __floats2half2_rn(v.x, v.y);
    dst[2 * j + 1] = __floats2half2_rn(v.z, v.w);
}

// ---------------- main GEMM ----------------
// C[e] = act(A[e] @ W[e] + bias[e]);  CTA 128x128, warp tile 64x32, BK=64.
// Next-stage cp.async issuance is spread between kk-steps (LSU burst smoothing).
template<int K, int NC, bool A_IDX, bool C_IDX, bool GELU, class CT>
__global__ void __launch_bounds__(256, 2) ffn_gemm(
    const __half* __restrict__ A,
    const __half* __restrict__ W,
    const float* __restrict__ bias,
    CT* __restrict__ C)
{
    extern __shared__ __half smem[];

    const int tid  = threadIdx.x;
    const int lane = tid & 31;
    const int wid  = tid >> 5;
    const int wm   = wid >> 2;             // 0..1  (64 rows)
    const int wn   = wid & 3;              // 0..3  (32 cols)
    const int qr   = lane >> 2;            // 0..7
    const int qc   = lane & 3;             // 0..3

    const int e  = blockIdx.z;
    const int m0 = blockIdx.y * BM;
    const int n0 = blockIdx.x * BN;

    // ---- cp.async geometry (4 chunks of A + 4 of W per thread per stage) ----
    const int arow0 = tid >> 3, akc = (tid & 7) << 3;
    const int wrow0 = tid >> 4, wnc = (tid & 15) << 3;

    const __half* gA;   // advanced by BK per chunk
    if (A_IDX) gA = A + xrow_off(m0 + arow0, e) + akc;
    else       gA = A + ((size_t)e * MMTOK + m0 + arow0) * (size_t)K + akc;
    const __half* gW = W + (size_t)e * K * NC + n0 + (size_t)wrow0 * NC + wnc;

    const uint32_t sbase = (uint32_t)__cvta_generic_to_shared(smem);
    const uint32_t sAoff = sbase + (uint32_t)(arow0 * APAD + akc) * 2;
    const uint32_t sWoff = sbase + (uint32_t)STAGES * A_ST_BYTES
                         + (uint32_t)(wrow0 * WPAD + wnc) * 2;

    // ---- ldmatrix per-lane base offsets (halves) ----
    const int matQ = lane >> 3;
    const int rowQ = lane & 7;
    const int a_lane_off = (wm * 64 + (matQ & 1) * 8 + rowQ) * APAD + (matQ >> 1) * 8;
    const int b_lane_off = ((matQ & 1) * 8 + rowQ) * WPAD + wn * 32 + (matQ >> 1) * 8;

    float acc[4][4][4];
    #pragma unroll
    for (int i = 0; i < 4; i++)
        #pragma unroll
        for (int j = 0; j < 4; j++)
            #pragma unroll
            for (int r = 0; r < 4; r++) acc[i][j][r] = 0.0f;

    constexpr int KCH = K / BK;

    auto issue_A = [&](int s) {
        uint32_t sa = sAoff + (uint32_t)s * A_ST_BYTES;
        #pragma unroll
        for (int t = 0; t < 4; t++)
            cp16(sa + (uint32_t)(t * 32 * APAD) * 2, gA + (size_t)t * 32 * K);
        gA += BK;
    };
    auto issue_W = [&](int s) {
        uint32_t sw = sWoff + (uint32_t)s * W_ST_BYTES;
        #pragma unroll
        for (int t = 0; t < 4; t++)
            cp16(sw + (uint32_t)(t * 16 * WPAD) * 2, gW + (size_t)t * 16 * NC);
        gW += (size_t)BK * NC;
    };

    // prologue: chunks 0,1 into stages 0,1
    issue_A(0); issue_W(0); cp_commit();
    issue_A(1); issue_W(1); cp_commit();

    int s = 0;
    #pragma unroll 1
    for (int c = 0; c < KCH; c++) {
        cp_wait<1>();             // stage s (chunk c) resident
        __syncthreads();          // publish copies + protect stage being overwritten

        const bool pf = (c + 2 < KCH);
        const int ws = (s + 2 >= STAGES) ? s + 2 - STAGES : s + 2;

        const uint32_t asb = sbase + (uint32_t)s * A_ST_BYTES + (uint32_t)a_lane_off * 2;
        const uint32_t wsb = sbase + (uint32_t)STAGES * A_ST_BYTES
                           + (uint32_t)s * W_ST_BYTES + (uint32_t)b_lane_off * 2;

        #pragma unroll
        for (int step = 0; step < BK / 16; step++) {
            const int kk = step * 16;
            uint32_t a[4][4];
            uint32_t b[2][4];
            #pragma unroll
            for (int i = 0; i < 4; i++)
                ldmA(a[i], asb + (uint32_t)(i * 16 * APAD + kk) * 2);
            #pragma unroll
            for (int j = 0; j < 2; j++)
                ldmB4(b[j], wsb + (uint32_t)(kk * WPAD + j * 16) * 2);
            #pragma unroll
            for (int i = 0; i < 4; i++)
                #pragma unroll
                for (int j = 0; j < 4; j++)
                    mma16816(acc[i][j], a[i], &b[j >> 1][(j & 1) * 2]);
            // spread next-stage issuance between kk-steps
            if (step == 0 && pf) issue_A(ws);
            if (step == 1 && pf) issue_W(ws);
        }
        cp_commit();              // one group per iteration (empty near tail)
        if (++s == STAGES) s = 0;
    }

    // ---------------- epilogue: bias (+gelu) + store ----------------
    #pragma unroll
    for (int i = 0; i < 4; i++) {
        #pragma unroll
        for (int hh = 0; hh < 2; hh++) {
            int m = m0 + wm * 64 + i * 16 + hh * 8 + qr;
            size_t crow;
            if (C_IDX) crow = xrow_off(m, e);
            else       crow = ((size_t)e * MMTOK + m) * (size_t)NC;
            #pragma unroll
            for (int j = 0; j < 4; j++) {
                int n = n0 + wn * 32 + j * 8 + qc * 2;
                float2 bv = *(const float2*)(bias + (size_t)e * NC + n);
                float vx = acc[i][j][hh * 2 + 0] + bv.x;
                float vy = acc[i][j][hh * 2 + 1] + bv.y;
                if (GELU) { vx = gelu_tanh(vx); vy = gelu_tanh(vy); }
                if constexpr (sizeof(CT) == 2) {
                    *(__half2*)((__half*)C + crow + n) = __floats2half2_rn(vx, vy);
                } else {
                    float2 o; o.x = vx; o.y = vy;
                    *(float2*)((float*)C + crow + n) = o;
                }
            }
        }
    }
}

// ---------------- host ----------------
extern "C" void kernel_launch(void* const* d_in, const int* in_sizes, int n_in,
                              void* d_out, int out_size)
{
    const float* x  = (const float*)d_in[0];   // (B,E,N,D)
    const float* w1 = (const float*)d_in[1];   // (E,D,H)
    const float* b1 = (const float*)d_in[2];   // (E,H)
    const float* w2 = (const float*)d_in[3];   // (E,H,D)
    const float* b2 = (const float*)d_in[4];   // (E,D)
    float* out = (float*)d_out;                // (B,E,N,D)

    void *ph, *pxh, *pw1, *pw2;
    cudaGetSymbolAddress(&ph,  g_h);
    cudaGetSymbolAddress(&pxh, g_xh);
    cudaGetSymbolAddress(&pw1, g_w1h);
    cudaGetSymbolAddress(&pw2, g_w2h);
    __half* h   = (__half*)ph;
    __half* xh  = (__half*)pxh;
    __half* w1h = (__half*)pw1;
    __half* w2h = (__half*)pw2;

    // prep: single fused fp16 conversion pass (x, w1, w2)
    {
        size_t total4 = NX4 + 2 * NW4;
        to_half_all<<<(unsigned)(total4 / 256), 256>>>(
            (const float4*)x,  (__half2*)xh,
            (const float4*)w1, (__half2*)w1h,
            (const float4*)w2, (__half2*)w2h);
    }

    cudaFuncSetAttribute(ffn_gemm<DD, HH, true,  false, true,  __half>,
                         cudaFuncAttributeMaxDynamicSharedMemorySize, SMEM_BYTES);
    cudaFuncSetAttribute(ffn_gemm<HH, DD, false, true,  false, float>,
                         cudaFuncAttributeMaxDynamicSharedMemorySize, SMEM_BYTES);

    // GEMM1: h = fp16(gelu(x @ w1 + b1))
    ffn_gemm<DD, HH, true, false, true, __half>
        <<<dim3(HH / BN, MMTOK / BM, EE), 256, SMEM_BYTES>>>(xh, w1h, b1, h);
    // GEMM2: out = h @ w2 + b2
    ffn_gemm<HH, DD, false, true, false, float>
        <<<dim3(DD / BN, MMTOK / BM, EE), 256, SMEM_BYTES>>>(h, w2h, b2, out);
}

// round 16
// speedup vs baseline: 1.3133x; 1.0005x over previous
#include <cuda_runtime.h>
#include <cuda_fp16.h>
#include <math.h>
#include <stdint.h>

// ---------------- problem constants ----------------
#define BBATCH 4
#define EE 8
#define NTOK 1024
#define DD 1024
#define HH 4096
#define MMTOK 4096          // B*N rows per expert

// ---------------- tile config (R7 core) ----------------
#define BM 128
#define BN 128
#define BK 64               // halves per k-chunk (128 B rows)
#define STAGES 3
#define APAD 72             // A smem row stride in halves (144 B)
#define WPAD 136            // W smem row stride in halves (272 B)

#define A_ST_BYTES (BM * APAD * 2)     // 18432
#define W_ST_BYTES (BK * WPAD * 2)     // 17408
#define SMEM_BYTES (STAGES * (A_ST_BYTES + W_ST_BYTES))   // 107520

// ---------------- device scratch (fp16 copies + hidden acts) ----------------
__device__ __align__(1024) __half g_h  [(size_t)EE * MMTOK * HH];
__device__ __align__(1024) __half g_xh [(size_t)BBATCH * EE * NTOK * DD];
__device__ __align__(1024) __half g_w1h[(size_t)EE * DD * HH];
__device__ __align__(1024) __half g_w2h[(size_t)EE * HH * DD];

// ---------------- helpers ----------------
__device__ __forceinline__ float gelu_tanh(float v) {
    const float c0 = 0.7978845608028654f;
    const float c1 = 0.044715f;
    float u = c0 * (v + c1 * v * v * v);
    return 0.5f * v * (1.0f + tanhf(u));
}
__device__ __forceinline__ size_t xrow_off(int m, int e) {
    return ((size_t)((m >> 10) * EE + e) * NTOK + (size_t)(m & (NTOK - 1))) * DD;
}
__device__ __forceinline__ void cp16(uint32_t smem_dst, const void* gsrc) {
    asm volatile("cp.async.cg.shared.global [%0], [%1], 16;" :: "r"(smem_dst), "l"(gsrc));
}
__device__ __forceinline__ void cp_commit() { asm volatile("cp.async.commit_group;"); }
template<int N> __device__ __forceinline__ void cp_wait() {
    asm volatile("cp.async.wait_group %0;" :: "n"(N));
}
__device__ __forceinline__ void ldmA(uint32_t* r, uint32_t addr) {
    asm volatile("ldmatrix.sync.aligned.m8n8.x4.shared.b16 {%0,%1,%2,%3}, [%4];"
                 : "=r"(r[0]), "=r"(r[1]), "=r"(r[2]), "=r"(r[3]) : "r"(addr));
}
__device__ __forceinline__ void ldmB4(uint32_t* r, uint32_t addr) {
    asm volatile("ldmatrix.sync.aligned.m8n8.x4.trans.shared.b16 {%0,%1,%2,%3}, [%4];"
                 : "=r"(r[0]), "=r"(r[1]), "=r"(r[2]), "=r"(r[3]) : "r"(addr));
}
__device__ __forceinline__ void mma16816(float* c, const uint32_t* a, const uint32_t* b) {
    asm volatile(
        "mma.sync.aligned.m16n8k16.row.col.f32.f16.f16.f32 "
        "{%0,%1,%2,%3}, {%4,%5,%6,%7}, {%8,%9}, {%0,%1,%2,%3};"
        : "+f"(c[0]), "+f"(c[1]), "+f"(c[2]), "+f"(c[3])
        : "r"(a[0]), "r"(a[1]), "r"(a[2]), "r"(a[3]), "r"(b[0]), "r"(b[1]));
}

// ---------------- prep: one fused fp32 -> fp16 (RN) conversion pass ----------------
#define NX4 ((size_t)BBATCH * EE * NTOK * DD / 4)   // 8388608 float4
#define NW4 ((size_t)EE * DD * HH / 4)              // 8388608 float4
__global__ __launch_bounds__(256) void to_half_all(
    const float4* __restrict__ x,  __half2* __restrict__ xh,
    const float4* __restrict__ w1, __half2* __restrict__ w1h,
    const float4* __restrict__ w2, __half2* __restrict__ w2h)
{
    size_t i = (size_t)blockIdx.x * blockDim.x + threadIdx.x;
    const float4* src;
    __half2* dst;
    size_t j;
    if (i < NX4)             { src = x;  dst = xh;  j = i; }
    else if (i < NX4 + NW4)  { src = w1; dst = w1h; j = i - NX4; }
    else                     { src = w2; dst = w2h; j = i - NX4 - NW4; }
    float4 v = src[j];
    dst[2 * j]     = __floats2half2_rn(v.x, v.y);
    dst[2 * j + 1] = __floats2half2_rn(v.z, v.w);
}

// ---------------- main GEMM ----------------
// C[e] = act(A[e] @ W[e] + bias[e]);  CTA 128x128, warp tile 64x32, BK=64.
// Next-stage cp.async issuance is spread between kk-steps (LSU burst smoothing).
template<int K, int NC, bool A_IDX, bool C_IDX, bool GELU, class CT>
__global__ void __launch_bounds__(256, 2) ffn_gemm(
    const __half* __restrict__ A,
    const __half* __restrict__ W,
    const float* __restrict__ bias,
    CT* __restrict__ C)
{
    extern __shared__ __half smem[];

    const int tid  = threadIdx.x;
    const int lane = tid & 31;
    const int wid  = tid >> 5;
    const int wm   = wid >> 2;             // 0..1  (64 rows)
    const int wn   = wid & 3;              // 0..3  (32 cols)
    const int qr   = lane >> 2;            // 0..7
    const int qc   = lane & 3;             // 0..3

    const int e  = blockIdx.z;
    const int m0 = blockIdx.y * BM;
    const int n0 = blockIdx.x * BN;

    // ---- cp.async geometry (4 chunks of A + 4 of W per thread per stage) ----
    const int arow0 = tid >> 3, akc = (tid & 7) << 3;
    const int wrow0 = tid >> 4, wnc = (tid & 15) << 3;

    const __half* gA;   // advanced by BK per chunk
    if (A_IDX) gA = A + xrow_off(m0 + arow0, e) + akc;
    else       gA = A + ((size_t)e * MMTOK + m0 + arow0) * (size_t)K + akc;
    const __half* gW = W + (size_t)e * K * NC + n0 + (size_t)wrow0 * NC + wnc;

    const uint32_t sbase = (uint32_t)__cvta_generic_to_shared(smem);
    const uint32_t sAoff = sbase + (uint32_t)(arow0 * APAD + akc) * 2;
    const uint32_t sWoff = sbase + (uint32_t)STAGES * A_ST_BYTES
                         + (uint32_t)(wrow0 * WPAD + wnc) * 2;

    // ---- ldmatrix per-lane base offsets (halves) ----
    const int matQ = lane >> 3;
    const int rowQ = lane & 7;
    const int a_lane_off = (wm * 64 + (matQ & 1) * 8 + rowQ) * APAD + (matQ >> 1) * 8;
    const int b_lane_off = ((matQ & 1) * 8 + rowQ) * WPAD + wn * 32 + (matQ >> 1) * 8;

    float acc[4][4][4];
    #pragma unroll
    for (int i = 0; i < 4; i++)
        #pragma unroll
        for (int j = 0; j < 4; j++)
            #pragma unroll
            for (int r = 0; r < 4; r++) acc[i][j][r] = 0.0f;

    constexpr int KCH = K / BK;

    auto issue_A = [&](int s) {
        uint32_t sa = sAoff + (uint32_t)s * A_ST_BYTES;
        #pragma unroll
        for (int t = 0; t < 4; t++)
            cp16(sa + (uint32_t)(t * 32 * APAD) * 2, gA + (size_t)t * 32 * K);
        gA += BK;
    };
    auto issue_W = [&](int s) {
        uint32_t sw = sWoff + (uint32_t)s * W_ST_BYTES;
        #pragma unroll
        for (int t = 0; t < 4; t++)
            cp16(sw + (uint32_t)(t * 16 * WPAD) * 2, gW + (size_t)t * 16 * NC);
        gW += (size_t)BK * NC;
    };

    // prologue: chunks 0,1 into stages 0,1
    issue_A(0); issue_W(0); cp_commit();
    issue_A(1); issue_W(1); cp_commit();

    int s = 0;
    #pragma unroll 1
    for (int c = 0; c < KCH; c++) {
        cp_wait<1>();             // stage s (chunk c) resident
        __syncthreads();          // publish copies + protect stage being overwritten

        const bool pf = (c + 2 < KCH);
        const int ws = (s + 2 >= STAGES) ? s + 2 - STAGES : s + 2;

        const uint32_t asb = sbase + (uint32_t)s * A_ST_BYTES + (uint32_t)a_lane_off * 2;
        const uint32_t wsb = sbase + (uint32_t)STAGES * A_ST_BYTES
                           + (uint32_t)s * W_ST_BYTES + (uint32_t)b_lane_off * 2;

        #pragma unroll
        for (int step = 0; step < BK / 16; step++) {
            const int kk = step * 16;
            uint32_t a[4][4];
            uint32_t b[2][4];
            #pragma unroll
            for (int i = 0; i < 4; i++)
                ldmA(a[i], asb + (uint32_t)(i * 16 * APAD + kk) * 2);
            #pragma unroll
            for (int j = 0; j < 2; j++)
                ldmB4(b[j], wsb + (uint32_t)(kk * WPAD + j * 16) * 2);
            #pragma unroll
            for (int i = 0; i < 4; i++)
                #pragma unroll
                for (int j = 0; j < 4; j++)
                    mma16816(acc[i][j], a[i], &b[j >> 1][(j & 1) * 2]);
            // spread next-stage issuance between kk-steps
            if (step == 0 && pf) issue_A(ws);
            if (step == 1 && pf) issue_W(ws);
        }
        cp_commit();              // one group per iteration (empty near tail)
        if (++s == STAGES) s = 0;
    }

    // ---------------- epilogue: bias (+gelu) + store ----------------
    #pragma unroll
    for (int i = 0; i < 4; i++) {
        #pragma unroll
        for (int hh = 0; hh < 2; hh++) {
            int m = m0 + wm * 64 + i * 16 + hh * 8 + qr;
            size_t crow;
            if (C_IDX) crow = xrow_off(m, e);
            else       crow = ((size_t)e * MMTOK + m) * (size_t)NC;
            #pragma unroll
            for (int j = 0; j < 4; j++) {
                int n = n0 + wn * 32 + j * 8 + qc * 2;
                float2 bv = *(const float2*)(bias + (size_t)e * NC + n);
                float vx = acc[i][j][hh * 2 + 0] + bv.x;
                float vy = acc[i][j][hh * 2 + 1] + bv.y;
                if (GELU) { vx = gelu_tanh(vx); vy = gelu_tanh(vy); }
                if constexpr (sizeof(CT) == 2) {
                    *(__half2*)((__half*)C + crow + n) = __floats2half2_rn(vx, vy);
                } else {
                    float2 o; o.x = vx; o.y = vy;
                    *(float2*)((float*)C + crow + n) = o;
                }
            }
        }
    }
}

// ---------------- host ----------------
extern "C" void kernel_launch(void* const* d_in, const int* in_sizes, int n_in,
                              void* d_out, int out_size)
{
    const float* x  = (const float*)d_in[0];   // (B,E,N,D)
    const float* w1 = (const float*)d_in[1];   // (E,D,H)
    const float* b1 = (const float*)d_in[2];   // (E,H)
    const float* w2 = (const float*)d_in[3];   // (E,H,D)
    const float* b2 = (const float*)d_in[4];   // (E,D)
    float* out = (float*)d_out;                // (B,E,N,D)

    void *ph, *pxh, *pw1, *pw2;
    cudaGetSymbolAddress(&ph,  g_h);
    cudaGetSymbolAddress(&pxh, g_xh);
    cudaGetSymbolAddress(&pw1, g_w1h);
    cudaGetSymbolAddress(&pw2, g_w2h);
    __half* h   = (__half*)ph;
    __half* xh  = (__half*)pxh;
    __half* w1h = (__half*)pw1;
    __half* w2h = (__half*)pw2;

    // prep: single fused fp16 conversion pass (x, w1, w2)
    {
        size_t total4 = NX4 + 2 * NW4;
        to_half_all<<<(unsigned)(total4 / 256), 256>>>(
            (const float4*)x,  (__half2*)xh,
            (const float4*)w1, (__half2*)w1h,
            (const float4*)w2, (__half2*)w2h);
    }

    cudaFuncSetAttribute(ffn_gemm<DD, HH, true,  false, true,  __half>,
                         cudaFuncAttributeMaxDynamicSharedMemorySize, SMEM_BYTES);
    cudaFuncSetAttribute(ffn_gemm<HH, DD, false, true,  false, float>,
                         cudaFuncAttributeMaxDynamicSharedMemorySize, SMEM_BYTES);

    // GEMM1: h = fp16(gelu(x @ w1 + b1))
    ffn_gemm<DD, HH, true, false, true, __half>
        <<<dim3(HH / BN, MMTOK / BM, EE), 256, SMEM_BYTES>>>(xh, w1h, b1, h);
    // GEMM2: out = h @ w2 + b2
    ffn_gemm<HH, DD, false, true, false, float>
        <<<dim3(DD / BN, MMTOK / BM, EE), 256, SMEM_BYTES>>>(h, w2h, b2, out);
}